// round 1
// baseline (speedup 1.0000x reference)
#include <cuda_runtime.h>
#include <math.h>

// ---------------------------------------------------------------------------
// LocalPseudoFeatLoss: B=2, C=19, H=W=128, CH=64, K=7, TOPK=8
// Inputs (metadata order):
//   0 logits_trg [2,19,128,128] f32
//   1 gt_src     [2,1,128,128]  i32
//   2 x_ema      [2,64,128,128] f32
//   3 x_src      [2,64,128,128] f32
//   4 mix_masks  [2,1,128,128]  f32
//   5 img_trg    [2,3,128,128]  f32 (unused)
// Output: 4 x f32
// ---------------------------------------------------------------------------

namespace {
constexpr int BB   = 2;
constexpr int NC   = 19;    // classes
constexpr int NCP  = 20;    // padded classes (float4-friendly, pad = 0)
constexpr int HH   = 128;
constexpr int WW   = 128;
constexpr int HWp  = HH * WW;
constexpr int FC   = 64;    // feature channels
constexpr int KK   = 7;
constexpr int K2   = KK * KK;
constexpr int NTOP = 9;     // TOPK + 1
constexpr int NBOT = 8;     // TOPK
constexpr int NPIX = BB * HWp;
constexpr float EPSV = 1e-8f;
}

// scratch (allocation-free rule: __device__ globals)
__device__ float  g_xs[NPIX * FC];    // x_src pixel-major
__device__ float  g_xe[NPIX * FC];    // x_ema pixel-major
__device__ float  g_pp[NPIX * NCP];   // softmax(logits) pixel-major, padded
__device__ float  g_rns[NPIX];        // 1/max(||x_src||, eps)
__device__ float  g_rne[NPIX];        // 1/max(||x_ema||, eps)
__device__ double g_acc[8];
// 0: sum_src_pos  1: cnt_src_pos  2: sum_src_neg  3: cnt_src_neg
// 4: sum_sim_pos  5: sum_sim_neg  6: cnt_trg_pixels

__global__ void k_zero() {
    if (threadIdx.x < 8) g_acc[threadIdx.x] = 0.0;
}

// transpose features to pixel-major, compute reciprocal norms, softmax(logits)
__global__ void k_prep(const float* __restrict__ logits,
                       const float* __restrict__ xe,
                       const float* __restrict__ xs) {
    int pix = blockIdx.x * blockDim.x + threadIdx.x;
    if (pix >= NPIX) return;
    int b  = pix / HWp;
    int hw = pix - b * HWp;

    {
        const float* base = xs + (size_t)b * FC * HWp + hw;
        float ss = 0.f;
        #pragma unroll
        for (int c = 0; c < FC; c++) {
            float v = base[(size_t)c * HWp];
            g_xs[(size_t)pix * FC + c] = v;
            ss = fmaf(v, v, ss);
        }
        g_rns[pix] = 1.f / fmaxf(sqrtf(ss), EPSV);
    }
    {
        const float* base = xe + (size_t)b * FC * HWp + hw;
        float ss = 0.f;
        #pragma unroll
        for (int c = 0; c < FC; c++) {
            float v = base[(size_t)c * HWp];
            g_xe[(size_t)pix * FC + c] = v;
            ss = fmaf(v, v, ss);
        }
        g_rne[pix] = 1.f / fmaxf(sqrtf(ss), EPSV);
    }
    {
        const float* lb = logits + (size_t)b * NC * HWp + hw;
        float l[NC];
        float mx = -3.4e38f;
        #pragma unroll
        for (int c = 0; c < NC; c++) {
            l[c] = lb[(size_t)c * HWp];
            mx = fmaxf(mx, l[c]);
        }
        float s = 0.f;
        #pragma unroll
        for (int c = 0; c < NC; c++) {
            l[c] = expf(l[c] - mx);
            s += l[c];
        }
        float inv = 1.f / s;
        #pragma unroll
        for (int c = 0; c < NC; c++)
            g_pp[(size_t)pix * NCP + c] = l[c] * inv;
        g_pp[(size_t)pix * NCP + NC] = 0.f;  // pad
    }
}

// ---- source pos/neg cosine-similarity masked means ----
__global__ void __launch_bounds__(128)
k_src(const int* __restrict__ gt) {
    int pix = blockIdx.x * blockDim.x + threadIdx.x;
    float sp = 0.f, sn = 0.f;
    int cp = 0, cn = 0;

    if (pix < NPIX) {
        int b  = pix / HWp;
        int hw = pix - b * HWp;
        int h  = hw / WW;
        int w  = hw - h * WW;
        int gc = gt[pix];
        if (gc != 255) {
            float4 f[16];
            const float4* cf = reinterpret_cast<const float4*>(g_xs + (size_t)pix * FC);
            #pragma unroll
            for (int i = 0; i < 16; i++) f[i] = cf[i];
            float rnc = g_rns[pix];

            #pragma unroll 1
            for (int k = 0; k < K2; k++) {
                int dy = k / KK - 3;
                int dx = k - (k / KK) * KK - 3;
                int hn = h + dy, wn = w + dx;
                float sim = 0.f;
                int   gn  = 0;   // zero-padded gt for OOB
                if ((unsigned)hn < (unsigned)HH && (unsigned)wn < (unsigned)WW) {
                    int pn = b * HWp + hn * WW + wn;
                    const float4* nf = reinterpret_cast<const float4*>(g_xs + (size_t)pn * FC);
                    float dot = 0.f;
                    #pragma unroll
                    for (int i = 0; i < 16; i++) {
                        float4 v = nf[i];
                        dot = fmaf(f[i].x, v.x, dot);
                        dot = fmaf(f[i].y, v.y, dot);
                        dot = fmaf(f[i].z, v.z, dot);
                        dot = fmaf(f[i].w, v.w, dot);
                    }
                    sim = dot * rnc * g_rns[pn];
                    gn  = gt[pn];
                }
                if (gn == gc) { sp += sim; cp++; }
                else          { sn += sim; cn++; }
            }
        }
    }

    // warp reduce
    #pragma unroll
    for (int off = 16; off; off >>= 1) {
        sp += __shfl_down_sync(0xffffffffu, sp, off);
        sn += __shfl_down_sync(0xffffffffu, sn, off);
        cp += __shfl_down_sync(0xffffffffu, cp, off);
        cn += __shfl_down_sync(0xffffffffu, cn, off);
    }
    __shared__ float sh[4][4];
    int warp = threadIdx.x >> 5, lane = threadIdx.x & 31;
    if (lane == 0) {
        sh[0][warp] = sp; sh[1][warp] = sn;
        sh[2][warp] = (float)cp; sh[3][warp] = (float)cn;
    }
    __syncthreads();
    if (threadIdx.x == 0) {
        float a = 0, b2 = 0, c2 = 0, d = 0;
        #pragma unroll
        for (int i = 0; i < 4; i++) {
            a += sh[0][i]; b2 += sh[1][i]; c2 += sh[2][i]; d += sh[3][i];
        }
        atomicAdd(&g_acc[0], (double)a);
        atomicAdd(&g_acc[1], (double)c2);
        atomicAdd(&g_acc[2], (double)b2);
        atomicAdd(&g_acc[3], (double)d);
    }
}

// ---- target: sim_ema + cross-agreement + fused top-9 / bottom-8 ----
__global__ void __launch_bounds__(128)
k_trg(const float* __restrict__ mix) {
    int pix = blockIdx.x * blockDim.x + threadIdx.x;
    float ssp = 0.f, ssn = 0.f;
    int cnt = 0;

    if (pix < NPIX) {
        if ((1.f - mix[pix]) > 0.5f) {
            cnt = 1;
            int b  = pix / HWp;
            int hw = pix - b * HWp;
            int h  = hw / WW;
            int w  = hw - h * WW;

            float4 f[16];
            const float4* cf = reinterpret_cast<const float4*>(g_xe + (size_t)pix * FC);
            #pragma unroll
            for (int i = 0; i < 16; i++) f[i] = cf[i];
            float rnc = g_rne[pix];

            float4 pc[5];
            const float4* cpv4 = reinterpret_cast<const float4*>(g_pp + (size_t)pix * NCP);
            #pragma unroll
            for (int i = 0; i < 5; i++) pc[i] = cpv4[i];

            // streaming selection (strict compares == JAX lowest-index tie-break)
            float tv[NTOP], tc[NTOP];   // descending top-9 of sim, paired cp
            float bv[NBOT], bc[NBOT];   // ascending bottom-8 of sim, paired cp
            #pragma unroll
            for (int i = 0; i < NTOP; i++) { tv[i] = -3.4e38f; tc[i] = 0.f; }
            #pragma unroll
            for (int i = 0; i < NBOT; i++) { bv[i] =  3.4e38f; bc[i] = 0.f; }

            #pragma unroll 1
            for (int k = 0; k < K2; k++) {
                int dy = k / KK - 3;
                int dx = k - (k / KK) * KK - 3;
                int hn = h + dy, wn = w + dx;
                float sim = 0.f;
                float cpx = 1.f / 19.f;   // OOB: uniform softmax of zero logits
                if ((unsigned)hn < (unsigned)HH && (unsigned)wn < (unsigned)WW) {
                    int pn = b * HWp + hn * WW + wn;
                    const float4* nf = reinterpret_cast<const float4*>(g_xe + (size_t)pn * FC);
                    float dot = 0.f;
                    #pragma unroll
                    for (int i = 0; i < 16; i++) {
                        float4 v = nf[i];
                        dot = fmaf(f[i].x, v.x, dot);
                        dot = fmaf(f[i].y, v.y, dot);
                        dot = fmaf(f[i].z, v.z, dot);
                        dot = fmaf(f[i].w, v.w, dot);
                    }
                    sim = dot * rnc * g_rne[pn];

                    const float4* np = reinterpret_cast<const float4*>(g_pp + (size_t)pn * NCP);
                    float d2 = 0.f;
                    #pragma unroll
                    for (int i = 0; i < 5; i++) {
                        float4 v = np[i];
                        d2 = fmaf(pc[i].x, v.x, d2);
                        d2 = fmaf(pc[i].y, v.y, d2);
                        d2 = fmaf(pc[i].z, v.z, d2);
                        d2 = fmaf(pc[i].w, v.w, d2);
                    }
                    cpx = d2;
                }

                // insert into descending top list (strict >)
                float vs = sim, vc = cpx;
                #pragma unroll
                for (int i = 0; i < NTOP; i++) {
                    if (vs > tv[i]) {
                        float t = tv[i]; tv[i] = vs; vs = t;
                        t = tc[i]; tc[i] = vc; vc = t;
                    }
                }
                // insert into ascending bottom list (strict <)
                float us = sim, uc = cpx;
                #pragma unroll
                for (int i = 0; i < NBOT; i++) {
                    if (us < bv[i]) {
                        float t = bv[i]; bv[i] = us; us = t;
                        t = bc[i]; bc[i] = uc; uc = t;
                    }
                }
            }

            #pragma unroll
            for (int i = 0; i < NTOP; i++) ssp = fmaf(tv[i], -tc[i], ssp);
            #pragma unroll
            for (int i = 0; i < NBOT; i++) ssn += (1.f - bv[i]) * (-(1.f - bc[i]));
        }
    }

    // warp reduce
    #pragma unroll
    for (int off = 16; off; off >>= 1) {
        ssp += __shfl_down_sync(0xffffffffu, ssp, off);
        ssn += __shfl_down_sync(0xffffffffu, ssn, off);
        cnt += __shfl_down_sync(0xffffffffu, cnt, off);
    }
    __shared__ float sh[3][4];
    int warp = threadIdx.x >> 5, lane = threadIdx.x & 31;
    if (lane == 0) {
        sh[0][warp] = ssp; sh[1][warp] = ssn; sh[2][warp] = (float)cnt;
    }
    __syncthreads();
    if (threadIdx.x == 0) {
        float a = 0, b2 = 0, c2 = 0;
        #pragma unroll
        for (int i = 0; i < 4; i++) { a += sh[0][i]; b2 += sh[1][i]; c2 += sh[2][i]; }
        atomicAdd(&g_acc[4], (double)a);
        atomicAdd(&g_acc[5], (double)b2);
        atomicAdd(&g_acc[6], (double)c2);
    }
}

__global__ void k_final(float* __restrict__ out) {
    if (threadIdx.x != 0) return;
    double src_pos = g_acc[0] / fmax(g_acc[1], 1.0);
    double src_neg = g_acc[2] / fmax(g_acc[3], 1.0);
    double sim_pos = g_acc[4] / fmax((double)NTOP * g_acc[6], 1.0);
    double sim_neg = g_acc[5] / fmax((double)NBOT * g_acc[6], 1.0);
    out[0] = (float)(-src_pos);
    out[1] = (float)( src_neg);
    out[2] = (float)( sim_pos);
    out[3] = (float)( sim_neg);
}

extern "C" void kernel_launch(void* const* d_in, const int* in_sizes, int n_in,
                              void* d_out, int out_size) {
    (void)in_sizes; (void)n_in; (void)out_size;
    const float* logits = (const float*)d_in[0];
    const int*   gt     = (const int*)d_in[1];
    const float* xe     = (const float*)d_in[2];
    const float* xs     = (const float*)d_in[3];
    const float* mix    = (const float*)d_in[4];
    float* out = (float*)d_out;

    k_zero<<<1, 32>>>();
    k_prep<<<(NPIX + 255) / 256, 256>>>(logits, xe, xs);
    k_src<<<(NPIX + 127) / 128, 128>>>(gt);
    k_trg<<<(NPIX + 127) / 128, 128>>>(mix);
    k_final<<<1, 32>>>(out);
}

// round 3
// speedup vs baseline: 1.1737x; 1.1737x over previous
#include <cuda_runtime.h>
#include <math.h>

// ---------------------------------------------------------------------------
// LocalPseudoFeatLoss: B=2, C=19, H=W=128, CH=64, K=7, TOPK=8
// ---------------------------------------------------------------------------

namespace {
constexpr int BB   = 2;
constexpr int NC   = 19;
constexpr int NCP  = 20;     // padded classes
constexpr int HH   = 128;
constexpr int WW   = 128;
constexpr int HWp  = HH * WW;
constexpr int FC   = 64;
constexpr int KK   = 7;
constexpr int K2   = KK * KK;
constexpr int NTOP = 9;
constexpr int NBOT = 8;
constexpr int NPIX = BB * HWp;
constexpr float EPSV = 1e-8f;
}

// scratch (~10.8 MB total, below the R1-passing footprint)
__device__ float  g_x[NPIX * FC];      // transposed features (reused: src, then ema)
__device__ float  g_pp[NPIX * NCP];    // softmax(logits) pixel-major, padded
__device__ float  g_rn[NPIX];          // 1/max(||x||,eps) (reused)
__device__ double g_acc[8];
// 0 sum_src_pos 1 cnt_src_pos 2 sum_src_neg 3 cnt_src_neg
// 4 sum_sim_pos 5 sum_sim_neg 6 cnt_trg

__device__ __forceinline__ float dot4(float4 a, float4 b) {
    float d = a.x * b.x;
    d = fmaf(a.y, b.y, d);
    d = fmaf(a.z, b.z, d);
    d = fmaf(a.w, b.w, d);
    return d;
}

__global__ void k_zero() {
    if (threadIdx.x < 8) g_acc[threadIdx.x] = 0.0;
}

// smem-staged transpose [C][HW] -> [pix][C] + reciprocal norms
__global__ void __launch_bounds__(256)
k_tr(const float* __restrict__ src) {
    __shared__ float sm[FC][33];
    int pix0 = blockIdx.x * 32;
    int b   = pix0 / HWp;
    int hw0 = pix0 - b * HWp;
    int t = threadIdx.x;

    int px = t & 31, cb = (t >> 5) * 8;
    const float* sp = src + (size_t)b * FC * HWp + hw0 + px;
    #pragma unroll
    for (int j = 0; j < 8; j++)
        sm[cb + j][px] = sp[(size_t)(cb + j) * HWp];
    __syncthreads();

    int px2 = t >> 3, part = t & 7;
    float v[8];
    float ss = 0.f;
    #pragma unroll
    for (int j = 0; j < 8; j++) {
        v[j] = sm[part * 8 + j][px2];
        ss = fmaf(v[j], v[j], ss);
    }
    float4* d = reinterpret_cast<float4*>(g_x + (size_t)(pix0 + px2) * FC + part * 8);
    d[0] = make_float4(v[0], v[1], v[2], v[3]);
    d[1] = make_float4(v[4], v[5], v[6], v[7]);
    #pragma unroll
    for (int o = 4; o; o >>= 1) ss += __shfl_xor_sync(0xffffffffu, ss, o);
    if (part == 0) g_rn[pix0 + px2] = 1.f / fmaxf(sqrtf(ss), EPSV);
}

// softmax per pixel -> pixel-major padded
__global__ void __launch_bounds__(256)
k_soft(const float* __restrict__ logits) {
    int pix = blockIdx.x * blockDim.x + threadIdx.x;
    if (pix >= NPIX) return;
    int b  = pix / HWp;
    int hw = pix - b * HWp;
    const float* lb = logits + (size_t)b * NC * HWp + hw;
    float l[NC];
    float mx = -3.4e38f;
    #pragma unroll
    for (int c = 0; c < NC; c++) {
        l[c] = lb[(size_t)c * HWp];
        mx = fmaxf(mx, l[c]);
    }
    float s = 0.f;
    #pragma unroll
    for (int c = 0; c < NC; c++) { l[c] = expf(l[c] - mx); s += l[c]; }
    float inv = 1.f / s;
    #pragma unroll
    for (int c = 0; c < NC; c++) g_pp[(size_t)pix * NCP + c] = l[c] * inv;
    g_pp[(size_t)pix * NCP + NC] = 0.f;
}

// ---- source loss: 16-lane group per pixel, deferred reduce ----
__global__ void __launch_bounds__(512)
k_src(const int* __restrict__ gt) {
    int bx = blockIdx.x;
    int b  = bx >> 9;
    int tt = bx & 511;
    int h0 = (tt >> 4) << 2;     // 32 h-tiles of 4
    int w0 = (tt & 15) << 3;     // 16 w-tiles of 8
    int g    = threadIdx.x >> 4;
    int lane = threadIdx.x & 15;
    unsigned gmask = 0xFFFFu << (threadIdx.x & 16);
    int h = h0 + (g >> 3), w = w0 + (g & 7);
    int pix = b * HWp + h * WW + w;

    float sp = 0.f, sn = 0.f;
    int cp = 0, cn = 0;
    int gc = gt[pix];
    if (gc != 255) {
        float4 f = reinterpret_cast<const float4*>(g_x + (size_t)pix * FC)[lane];
        float rnc = g_rn[pix];
        #pragma unroll 1
        for (int ky = 0; ky < KK; ky++) {
            int hn = h + ky - 3;
            bool rv = (unsigned)hn < (unsigned)HH;
            int hc = min(max(hn, 0), HH - 1);
            #pragma unroll
            for (int kx = 0; kx < KK; kx++) {
                int wn = w + kx - 3;
                bool ok = rv && ((unsigned)wn < (unsigned)WW);
                int wc = min(max(wn, 0), WW - 1);
                int pn = b * HWp + hc * WW + wc;    // clamped: uniform flow
                float4 nf = reinterpret_cast<const float4*>(g_x + (size_t)pn * FC)[lane];
                float contrib = dot4(f, nf) * (rnc * g_rn[pn]);
                int gn = gt[pn];
                if (!ok) { contrib = 0.f; gn = 0; }
                if (gn == gc) { sp += contrib; cp++; }
                else          { sn += contrib; cn++; }
            }
        }
        #pragma unroll
        for (int o = 8; o; o >>= 1) {
            sp += __shfl_xor_sync(gmask, sp, o);
            sn += __shfl_xor_sync(gmask, sn, o);
        }
    }
    __shared__ float sa[4];
    if (threadIdx.x < 4) sa[threadIdx.x] = 0.f;
    __syncthreads();
    if (gc != 255 && lane == 0) {
        atomicAdd(&sa[0], sp);
        atomicAdd(&sa[1], (float)cp);
        atomicAdd(&sa[2], sn);
        atomicAdd(&sa[3], (float)cn);
    }
    __syncthreads();
    if (threadIdx.x == 0) {
        atomicAdd(&g_acc[0], (double)sa[0]);
        atomicAdd(&g_acc[1], (double)sa[1]);
        atomicAdd(&g_acc[2], (double)sa[2]);
        atomicAdd(&g_acc[3], (double)sa[3]);
    }
}

// ---- target: fused sim/cross-prob (lane-parallel) + top-k (smem staging) ----
__global__ void __launch_bounds__(256)
k_trg(const float* __restrict__ mix) {
    __shared__ float sm_s[K2][17];
    __shared__ float sm_c[K2][17];
    __shared__ float sh[3];

    int bx = blockIdx.x;              // 2048 blocks
    int b  = bx >> 10;
    int tt = bx & 1023;               // 32x32 tiles of 4x4
    int h0 = (tt >> 5) << 2;
    int w0 = (tt & 31) << 2;
    int g    = threadIdx.x >> 4;      // 0..15 (pixel within tile)
    int lane = threadIdx.x & 15;
    unsigned gmask = 0xFFFFu << (threadIdx.x & 16);
    int h = h0 + (g >> 2), w = w0 + (g & 3);
    int pix = b * HWp + h * WW + w;

    bool act = (1.f - mix[pix]) > 0.5f;

    // ---- phase 1: 16 lanes cooperate on one pixel's 49 neighbors ----
    if (act) {
        float4 f = reinterpret_cast<const float4*>(g_x + (size_t)pix * FC)[lane];
        float rnc = g_rn[pix];
        float4 pc = (lane < 5)
            ? reinterpret_cast<const float4*>(g_pp + (size_t)pix * NCP)[lane]
            : make_float4(0.f, 0.f, 0.f, 0.f);

        int k = 0;
        #pragma unroll 1
        for (int ky = 0; ky < KK; ky++) {
            int hn = h + ky - 3;
            bool rv = (unsigned)hn < (unsigned)HH;
            int hc = min(max(hn, 0), HH - 1);
            #pragma unroll
            for (int kx = 0; kx < KK; kx++, k++) {
                int wn = w + kx - 3;
                bool ok = rv && ((unsigned)wn < (unsigned)WW);
                int wc = min(max(wn, 0), WW - 1);
                int pn = b * HWp + hc * WW + wc;
                float4 nf = reinterpret_cast<const float4*>(g_x + (size_t)pn * FC)[lane];
                float pd = dot4(f, nf);
                float4 np = (lane < 5)
                    ? reinterpret_cast<const float4*>(g_pp + (size_t)pn * NCP)[lane]
                    : make_float4(0.f, 0.f, 0.f, 0.f);
                float pq = dot4(pc, np);
                #pragma unroll
                for (int o = 8; o; o >>= 1) {
                    pd += __shfl_xor_sync(gmask, pd, o);
                    pq += __shfl_xor_sync(gmask, pq, o);
                }
                if (lane == 0) {
                    sm_s[k][g] = ok ? pd * (rnc * g_rn[pn]) : 0.f;
                    sm_c[k][g] = ok ? pq : (1.f / 19.f);
                }
            }
        }
    }
    if (threadIdx.x < 3) sh[threadIdx.x] = 0.f;
    __syncthreads();

    // ---- phase 2: threads 0..15 each select top-9 / bottom-8 for one pixel ----
    if (threadIdx.x < 16) {
        int t = threadIdx.x;
        int h2 = h0 + (t >> 2), w2 = w0 + (t & 3);
        int p2 = b * HWp + h2 * WW + w2;
        float ssp = 0.f, ssn = 0.f, cnt = 0.f;
        if ((1.f - mix[p2]) > 0.5f) {
            cnt = 1.f;
            float tv[NTOP], tc[NTOP], bv[NBOT], bc[NBOT];
            #pragma unroll
            for (int i = 0; i < NTOP; i++) { tv[i] = -3.4e38f; tc[i] = 0.f; }
            #pragma unroll
            for (int i = 0; i < NBOT; i++) { bv[i] =  3.4e38f; bc[i] = 0.f; }
            #pragma unroll 1
            for (int k = 0; k < K2; k++) {
                float vs = sm_s[k][t];
                float vc = sm_c[k][t];
                float us = vs, uc = vc;
                #pragma unroll
                for (int i = 0; i < NTOP; i++) {   // strict > : JAX tie-break
                    if (vs > tv[i]) {
                        float x = tv[i]; tv[i] = vs; vs = x;
                        x = tc[i]; tc[i] = vc; vc = x;
                    }
                }
                #pragma unroll
                for (int i = 0; i < NBOT; i++) {   // strict <
                    if (us < bv[i]) {
                        float x = bv[i]; bv[i] = us; us = x;
                        x = bc[i]; bc[i] = uc; uc = x;
                    }
                }
            }
            #pragma unroll
            for (int i = 0; i < NTOP; i++) ssp = fmaf(tv[i], -tc[i], ssp);
            #pragma unroll
            for (int i = 0; i < NBOT; i++) ssn += (1.f - bv[i]) * (-(1.f - bc[i]));
        }
        #pragma unroll
        for (int o = 8; o; o >>= 1) {
            ssp += __shfl_down_sync(0x0000FFFFu, ssp, o);
            ssn += __shfl_down_sync(0x0000FFFFu, ssn, o);
            cnt += __shfl_down_sync(0x0000FFFFu, cnt, o);
        }
        if (t == 0) { sh[0] = ssp; sh[1] = ssn; sh[2] = cnt; }
    }
    __syncthreads();
    if (threadIdx.x == 0) {
        atomicAdd(&g_acc[4], (double)sh[0]);
        atomicAdd(&g_acc[5], (double)sh[1]);
        atomicAdd(&g_acc[6], (double)sh[2]);
    }
}

__global__ void k_final(float* __restrict__ out) {
    if (threadIdx.x != 0) return;
    double src_pos = g_acc[0] / fmax(g_acc[1], 1.0);
    double src_neg = g_acc[2] / fmax(g_acc[3], 1.0);
    double sim_pos = g_acc[4] / fmax((double)NTOP * g_acc[6], 1.0);
    double sim_neg = g_acc[5] / fmax((double)NBOT * g_acc[6], 1.0);
    out[0] = (float)(-src_pos);
    out[1] = (float)( src_neg);
    out[2] = (float)( sim_pos);
    out[3] = (float)( sim_neg);
}

extern "C" void kernel_launch(void* const* d_in, const int* in_sizes, int n_in,
                              void* d_out, int out_size) {
    (void)in_sizes; (void)n_in; (void)out_size;
    const float* logits = (const float*)d_in[0];
    const int*   gt     = (const int*)d_in[1];
    const float* xe     = (const float*)d_in[2];
    const float* xs     = (const float*)d_in[3];
    const float* mix    = (const float*)d_in[4];
    float* out = (float*)d_out;

    k_zero<<<1, 32>>>();
    k_soft<<<NPIX / 256, 256>>>(logits);
    k_tr<<<NPIX / 32, 256>>>(xs);      // g_x/g_rn <- x_src
    k_src<<<1024, 512>>>(gt);
    k_tr<<<NPIX / 32, 256>>>(xe);      // g_x/g_rn <- x_ema (reuse buffers)
    k_trg<<<2048, 256>>>(mix);
    k_final<<<1, 32>>>(out);
}

// round 4
// speedup vs baseline: 1.7025x; 1.4506x over previous
#include <cuda_runtime.h>
#include <math.h>

// ---------------------------------------------------------------------------
// LocalPseudoFeatLoss: B=2, C=19, H=W=128, CH=64, K=7, TOPK=8
// ---------------------------------------------------------------------------

namespace {
constexpr int NC   = 19;
constexpr int NCP  = 20;     // padded classes
constexpr int HH   = 128;
constexpr int WW   = 128;
constexpr int HWp  = HH * WW;
constexpr int FC   = 64;
constexpr int KK   = 7;
constexpr int K2   = KK * KK;
constexpr int NTOP = 9;
constexpr int NBOT = 8;
constexpr int NPIX = 2 * HWp;
constexpr float EPSV = 1e-8f;
constexpr int FB = FC * 4;    // feature row bytes
constexpr int PB = NCP * 4;   // prob row bytes
}

// scratch (~10.6 MB, same footprint class as R3 which passed)
__device__ float  g_x[NPIX * FC];      // PRE-NORMALIZED features (src, then ema)
__device__ float  g_pp[NPIX * NCP];    // softmax(logits), pixel-major, padded
__device__ double g_acc[8];
// 0 sum_src_pos 1 cnt_src_pos 2 sum_src_neg 3 cnt_src_neg
// 4 sum_sim_pos 5 sum_sim_neg 6 cnt_trg

__device__ __forceinline__ float dot4(float4 a, float4 b) {
    float d = a.x * b.x;
    d = fmaf(a.y, b.y, d);
    d = fmaf(a.z, b.z, d);
    d = fmaf(a.w, b.w, d);
    return d;
}

// Reduce 8 values across 16 lanes (segmented exchange tree).
// On return, lanes {2n, 2n+1} both hold total of value n.
__device__ __forceinline__ float tree8(float v[8], unsigned mask, int lane) {
    {   bool hi = (lane & 8) != 0;
        #pragma unroll
        for (int j = 0; j < 4; j++) {
            float mine = hi ? v[j] : v[j + 4];
            float kept = hi ? v[j + 4] : v[j];
            v[j] = kept + __shfl_xor_sync(mask, mine, 8);
        } }
    {   bool hi = (lane & 4) != 0;
        #pragma unroll
        for (int j = 0; j < 2; j++) {
            float mine = hi ? v[j] : v[j + 2];
            float kept = hi ? v[j + 2] : v[j];
            v[j] = kept + __shfl_xor_sync(mask, mine, 4);
        } }
    {   bool hi = (lane & 2) != 0;
        float mine = hi ? v[0] : v[1];
        float kept = hi ? v[1] : v[0];
        v[0] = kept + __shfl_xor_sync(mask, mine, 2);
    }
    v[0] += __shfl_xor_sync(mask, v[0], 1);
    return v[0];
}

__global__ void k_zero() {
    if (threadIdx.x < 8) g_acc[threadIdx.x] = 0.0;
}

// transpose [C][HW] -> [pix][C], PRE-NORMALIZED by 1/max(||x||,eps)
__global__ void __launch_bounds__(256)
k_tr(const float* __restrict__ src) {
    __shared__ float sm[FC][33];
    int pix0 = blockIdx.x * 32;
    int b   = pix0 / HWp;
    int hw0 = pix0 - b * HWp;
    int t = threadIdx.x;

    int px = t & 31, cb = (t >> 5) * 8;
    const float* sp = src + (size_t)b * FC * HWp + hw0 + px;
    #pragma unroll
    for (int j = 0; j < 8; j++)
        sm[cb + j][px] = sp[(size_t)(cb + j) * HWp];
    __syncthreads();

    int px2 = t >> 3, part = t & 7;
    float v[8];
    float ss = 0.f;
    #pragma unroll
    for (int j = 0; j < 8; j++) {
        v[j] = sm[part * 8 + j][px2];
        ss = fmaf(v[j], v[j], ss);
    }
    #pragma unroll
    for (int o = 4; o; o >>= 1) ss += __shfl_xor_sync(0xffffffffu, ss, o);
    float rn = 1.f / fmaxf(sqrtf(ss), EPSV);
    float4* d = reinterpret_cast<float4*>(g_x + (size_t)(pix0 + px2) * FC + part * 8);
    d[0] = make_float4(v[0] * rn, v[1] * rn, v[2] * rn, v[3] * rn);
    d[1] = make_float4(v[4] * rn, v[5] * rn, v[6] * rn, v[7] * rn);
}

// softmax per pixel -> pixel-major padded
__global__ void __launch_bounds__(256)
k_soft(const float* __restrict__ logits) {
    int pix = blockIdx.x * blockDim.x + threadIdx.x;
    if (pix >= NPIX) return;
    int b  = pix / HWp;
    int hw = pix - b * HWp;
    const float* lb = logits + (size_t)b * NC * HWp + hw;
    float l[NC];
    float mx = -3.4e38f;
    #pragma unroll
    for (int c = 0; c < NC; c++) {
        l[c] = lb[(size_t)c * HWp];
        mx = fmaxf(mx, l[c]);
    }
    float s = 0.f;
    #pragma unroll
    for (int c = 0; c < NC; c++) { l[c] = expf(l[c] - mx); s += l[c]; }
    float inv = 1.f / s;
    #pragma unroll
    for (int c = 0; c < NC; c++) g_pp[(size_t)pix * NCP + c] = l[c] * inv;
    g_pp[(size_t)pix * NCP + NC] = 0.f;
}

// ---- source loss: 16 lanes/pixel, deferred reduce, interior fast path ----
__global__ void __launch_bounds__(512)
k_src(const int* __restrict__ gt) {
    int bx = blockIdx.x;
    int b  = bx >> 9;
    int tt = bx & 511;
    int h0 = (tt >> 4) << 2;     // 32 h-tiles of 4
    int w0 = (tt & 15) << 3;     // 16 w-tiles of 8
    int g    = threadIdx.x >> 4;
    int lane = threadIdx.x & 15;
    unsigned gmask = 0xFFFFu << (threadIdx.x & 16);
    int h = h0 + (g >> 3), w = w0 + (g & 7);
    int pix = b * HWp + h * WW + w;

    bool interior = (h0 >= 4) && (h0 <= 120) && (w0 >= 8) && (w0 <= 112);

    float sp = 0.f, sn = 0.f;
    float cp = 0.f, cn = 0.f;
    int gc = gt[pix];
    if (gc != 255) {
        const char* Pl = (const char*)g_x + (size_t)pix * FB + lane * 16;
        float4 f = *(const float4*)Pl;
        if (interior) {
            float tot = 0.f, spp = 0.f;
            int cpp = 0;
            #pragma unroll 1
            for (int ky = 0; ky < KK; ky++) {
                const char* Pr = Pl + (ptrdiff_t)(ky - 3) * (WW * FB);
                const int* Pg = gt + pix + (ky - 3) * WW;
                #pragma unroll
                for (int kx = 0; kx < KK; kx++) {
                    float4 nf = *(const float4*)(Pr + (kx - 3) * FB);
                    float s = dot4(f, nf);
                    int gn = Pg[kx - 3];
                    tot += s;
                    if (gn == gc) { spp += s; cpp++; }
                }
            }
            sp = spp; sn = tot - spp;
            cp = (float)cpp; cn = (float)(K2 - cpp);
        } else {
            int cpp = 0, cnn = 0;
            #pragma unroll 1
            for (int ky = 0; ky < KK; ky++) {
                int hn = h + ky - 3;
                bool rv = (unsigned)hn < (unsigned)HH;
                int hc = min(max(hn, 0), HH - 1);
                #pragma unroll
                for (int kx = 0; kx < KK; kx++) {
                    int wn = w + kx - 3;
                    bool ok = rv && ((unsigned)wn < (unsigned)WW);
                    int wc = min(max(wn, 0), WW - 1);
                    int pn = b * HWp + hc * WW + wc;
                    float4 nf = *(const float4*)((const char*)g_x + (size_t)pn * FB + lane * 16);
                    float s = dot4(f, nf);
                    int gn = gt[pn];
                    if (!ok) { s = 0.f; gn = 0; }
                    if (gn == gc) { sp += s; cpp++; }
                    else          { sn += s; cnn++; }
                }
            }
            cp = (float)cpp; cn = (float)cnn;
        }
        #pragma unroll
        for (int o = 8; o; o >>= 1) {
            sp += __shfl_xor_sync(gmask, sp, o);
            sn += __shfl_xor_sync(gmask, sn, o);
        }
    }
    __shared__ float sa[4];
    if (threadIdx.x < 4) sa[threadIdx.x] = 0.f;
    __syncthreads();
    if (gc != 255 && lane == 0) {
        atomicAdd(&sa[0], sp);
        atomicAdd(&sa[1], cp);
        atomicAdd(&sa[2], sn);
        atomicAdd(&sa[3], cn);
    }
    __syncthreads();
    if (threadIdx.x == 0) {
        atomicAdd(&g_acc[0], (double)sa[0]);
        atomicAdd(&g_acc[1], (double)sa[1]);
        atomicAdd(&g_acc[2], (double)sa[2]);
        atomicAdd(&g_acc[3], (double)sa[3]);
    }
}

// ---- target: fused sim/cross-prob + top-k, interior fast path + tree reduce ----
__global__ void __launch_bounds__(256)
k_trg(const float* __restrict__ mix) {
    __shared__ float sm_s[K2][17];
    __shared__ float sm_c[K2][17];

    int bx = blockIdx.x;              // 2048 blocks
    int b  = bx >> 10;
    int tt = bx & 1023;               // 32x32 tiles of 4x4
    int h0 = (tt >> 5) << 2;
    int w0 = (tt & 31) << 2;
    int g    = threadIdx.x >> 4;      // 0..15 pixel in tile
    int lane = threadIdx.x & 15;
    unsigned gmask = 0xFFFFu << (threadIdx.x & 16);
    int h = h0 + (g >> 2), w = w0 + (g & 3);
    int pix = b * HWp + h * WW + w;

    bool interior = (h0 >= 4) && (h0 <= 120) && (w0 >= 4) && (w0 <= 120);
    bool act = (1.f - mix[pix]) > 0.5f;

    // ---- phase 1 ----
    if (act) {
        const char* Pl = (const char*)g_x + (size_t)pix * FB + lane * 16;
        const char* Ppl = (const char*)g_pp + (size_t)pix * PB + lane * 16;
        float4 f = *(const float4*)Pl;
        float4 pc = (lane < 5) ? *(const float4*)Ppl
                               : make_float4(0.f, 0.f, 0.f, 0.f);
        if (interior) {
            #pragma unroll
            for (int c = 0; c < 6; c++) {            // 6 chunks of 8 neighbors
                float sv[8], cv[8];
                #pragma unroll
                for (int n = 0; n < 8; n++) {
                    int k  = c * 8 + n;              // compile-time
                    int dy = k / KK - 3;
                    int dx = k - (k / KK) * KK - 3;
                    int off = dy * WW + dx;          // compile-time
                    float4 nf = *(const float4*)(Pl + (ptrdiff_t)off * FB);
                    sv[n] = dot4(f, nf);
                    float4 np = (lane < 5)
                        ? *(const float4*)(Ppl + (ptrdiff_t)off * PB)
                        : make_float4(0.f, 0.f, 0.f, 0.f);
                    cv[n] = dot4(pc, np);
                }
                float s0 = tree8(sv, gmask, lane);
                float c0 = tree8(cv, gmask, lane);
                if (!(lane & 1)) {
                    int k = c * 8 + (lane >> 1);
                    sm_s[k][g] = s0;
                    sm_c[k][g] = c0;
                }
            }
            {   // straggler k = 48 (dy=3, dx=3)
                int off = 3 * WW + 3;
                float4 nf = *(const float4*)(Pl + (ptrdiff_t)off * FB);
                float pd = dot4(f, nf);
                float4 np = (lane < 5)
                    ? *(const float4*)(Ppl + (ptrdiff_t)off * PB)
                    : make_float4(0.f, 0.f, 0.f, 0.f);
                float pq = dot4(pc, np);
                #pragma unroll
                for (int o = 8; o; o >>= 1) {
                    pd += __shfl_xor_sync(gmask, pd, o);
                    pq += __shfl_xor_sync(gmask, pq, o);
                }
                if (lane == 0) { sm_s[48][g] = pd; sm_c[48][g] = pq; }
            }
        } else {
            int k = 0;
            #pragma unroll 1
            for (int ky = 0; ky < KK; ky++) {
                int hn = h + ky - 3;
                bool rv = (unsigned)hn < (unsigned)HH;
                int hc = min(max(hn, 0), HH - 1);
                #pragma unroll
                for (int kx = 0; kx < KK; kx++, k++) {
                    int wn = w + kx - 3;
                    bool ok = rv && ((unsigned)wn < (unsigned)WW);
                    int wc = min(max(wn, 0), WW - 1);
                    int pn = b * HWp + hc * WW + wc;
                    float4 nf = *(const float4*)((const char*)g_x + (size_t)pn * FB + lane * 16);
                    float pd = dot4(f, nf);
                    float4 np = (lane < 5)
                        ? *(const float4*)((const char*)g_pp + (size_t)pn * PB + lane * 16)
                        : make_float4(0.f, 0.f, 0.f, 0.f);
                    float pq = dot4(pc, np);
                    #pragma unroll
                    for (int o = 8; o; o >>= 1) {
                        pd += __shfl_xor_sync(gmask, pd, o);
                        pq += __shfl_xor_sync(gmask, pq, o);
                    }
                    if (lane == 0) {
                        sm_s[k][g] = ok ? pd : 0.f;
                        sm_c[k][g] = ok ? pq : (1.f / 19.f);
                    }
                }
            }
        }
    }
    __syncthreads();

    // ---- phase 2: threads 0..15 = top-9, threads 16..31 = bottom-8 ----
    float ssp = 0.f, ssn = 0.f, cnt = 0.f;
    if (threadIdx.x < 32) {
        int t = threadIdx.x & 15;
        bool isTop = threadIdx.x < 16;
        int h2 = h0 + (t >> 2), w2 = w0 + (t & 3);
        int p2 = b * HWp + h2 * WW + w2;
        if ((1.f - mix[p2]) > 0.5f) {
            if (isTop) {
                cnt = 1.f;
                float tv[NTOP], tc[NTOP];
                #pragma unroll
                for (int i = 0; i < NTOP; i++) { tv[i] = -3.4e38f; tc[i] = 0.f; }
                #pragma unroll 1
                for (int k = 0; k < K2; k++) {
                    float vs = sm_s[k][t];
                    float vc = sm_c[k][t];
                    #pragma unroll
                    for (int i = 0; i < NTOP; i++) {   // strict > : JAX tie-break
                        if (vs > tv[i]) {
                            float x = tv[i]; tv[i] = vs; vs = x;
                            x = tc[i]; tc[i] = vc; vc = x;
                        }
                    }
                }
                #pragma unroll
                for (int i = 0; i < NTOP; i++) ssp = fmaf(tv[i], -tc[i], ssp);
            } else {
                float bv[NBOT], bc[NBOT];
                #pragma unroll
                for (int i = 0; i < NBOT; i++) { bv[i] = 3.4e38f; bc[i] = 0.f; }
                #pragma unroll 1
                for (int k = 0; k < K2; k++) {
                    float us = sm_s[k][t];
                    float uc = sm_c[k][t];
                    #pragma unroll
                    for (int i = 0; i < NBOT; i++) {   // strict <
                        if (us < bv[i]) {
                            float x = bv[i]; bv[i] = us; us = x;
                            x = bc[i]; bc[i] = uc; uc = x;
                        }
                    }
                }
                #pragma unroll
                for (int i = 0; i < NBOT; i++) ssn += (1.f - bv[i]) * (-(1.f - bc[i]));
            }
        }
        #pragma unroll
        for (int o = 16; o; o >>= 1) {
            ssp += __shfl_xor_sync(0xffffffffu, ssp, o);
            ssn += __shfl_xor_sync(0xffffffffu, ssn, o);
            cnt += __shfl_xor_sync(0xffffffffu, cnt, o);
        }
        if (threadIdx.x == 0) {
            atomicAdd(&g_acc[4], (double)ssp);
            atomicAdd(&g_acc[5], (double)ssn);
            atomicAdd(&g_acc[6], (double)cnt);
        }
    }
}

__global__ void k_final(float* __restrict__ out) {
    if (threadIdx.x != 0) return;
    double src_pos = g_acc[0] / fmax(g_acc[1], 1.0);
    double src_neg = g_acc[2] / fmax(g_acc[3], 1.0);
    double sim_pos = g_acc[4] / fmax((double)NTOP * g_acc[6], 1.0);
    double sim_neg = g_acc[5] / fmax((double)NBOT * g_acc[6], 1.0);
    out[0] = (float)(-src_pos);
    out[1] = (float)( src_neg);
    out[2] = (float)( sim_pos);
    out[3] = (float)( sim_neg);
}

extern "C" void kernel_launch(void* const* d_in, const int* in_sizes, int n_in,
                              void* d_out, int out_size) {
    (void)in_sizes; (void)n_in; (void)out_size;
    const float* logits = (const float*)d_in[0];
    const int*   gt     = (const int*)d_in[1];
    const float* xe     = (const float*)d_in[2];
    const float* xs     = (const float*)d_in[3];
    const float* mix    = (const float*)d_in[4];
    float* out = (float*)d_out;

    k_zero<<<1, 32>>>();
    k_soft<<<NPIX / 256, 256>>>(logits);
    k_tr<<<NPIX / 32, 256>>>(xs);      // g_x <- normalized x_src
    k_src<<<1024, 512>>>(gt);
    k_tr<<<NPIX / 32, 256>>>(xe);      // g_x <- normalized x_ema
    k_trg<<<2048, 256>>>(mix);
    k_final<<<1, 32>>>(out);
}